// round 1
// baseline (speedup 1.0000x reference)
#include <cuda_runtime.h>

// MaxPool 2x2, stride 2, input (16, 64, 512, 512) fp32 -> output (16, 64, 256, 256) fp32.
// Pure HBM-streaming: each thread computes one float4 of output (4 pooled values)
// from 4x float4 input loads (LDG.128) and one STG.128 store.

#define IN_H 512
#define IN_W 512
#define OUT_H 256
#define OUT_W 256
#define BC (16 * 64)  // batch * channels planes

// float4 units per input row: 512/4 = 128
#define IN_ROW_F4 128
// float4 outputs per output row: 256/4 = 64
#define OUT_ROW_F4 64

__global__ void maxpool2x2_kernel(const float4* __restrict__ in4,
                                  float4* __restrict__ out4) {
    // total float4 outputs = BC * OUT_H * OUT_ROW_F4 = 1024*256*64 = 16,777,216
    unsigned tid = blockIdx.x * blockDim.x + threadIdx.x;

    unsigned ox4 = tid & (OUT_ROW_F4 - 1);          // [0, 64)
    unsigned rest = tid >> 6;                       // / 64
    unsigned oy = rest & (OUT_H - 1);               // [0, 256)
    unsigned bc = rest >> 8;                        // [0, 1024)

    // Input base in float4 units: plane offset + row(2*oy) + col(8*ox4 floats = 2*ox4 f4)
    unsigned ibase = bc * (IN_H * IN_ROW_F4) + (oy * 2) * IN_ROW_F4 + ox4 * 2;

    float4 r0a = in4[ibase];
    float4 r0b = in4[ibase + 1];
    float4 r1a = in4[ibase + IN_ROW_F4];
    float4 r1b = in4[ibase + IN_ROW_F4 + 1];

    float4 o;
    o.x = fmaxf(fmaxf(r0a.x, r0a.y), fmaxf(r1a.x, r1a.y));
    o.y = fmaxf(fmaxf(r0a.z, r0a.w), fmaxf(r1a.z, r1a.w));
    o.z = fmaxf(fmaxf(r0b.x, r0b.y), fmaxf(r1b.x, r1b.y));
    o.w = fmaxf(fmaxf(r0b.z, r0b.w), fmaxf(r1b.z, r1b.w));

    out4[tid] = o;
}

extern "C" void kernel_launch(void* const* d_in, const int* in_sizes, int n_in,
                              void* d_out, int out_size) {
    const float4* in4 = (const float4*)d_in[0];
    float4* out4 = (float4*)d_out;

    // total float4 outputs
    const unsigned total = BC * OUT_H * OUT_ROW_F4;  // 16,777,216
    const int threads = 256;
    const unsigned blocks = total / threads;         // 65,536

    maxpool2x2_kernel<<<blocks, threads>>>(in4, out4);
}